// round 16
// baseline (speedup 1.0000x reference)
#include <cuda_runtime.h>
#include <cuda_fp16.h>
#include <cstdint>
#include <math.h>

#define TT      8192
#define LSEQ    4096
#define NBATCH  2
#define DMODEL  2048
#define DINNER  4096
#define DSTATE  128
#define DCONV   4
#define NH      64
#define HD      64
#define CHUNKSZ 64
#define NCHUNK  64
#define CONVDIM 4352
#define DPROJ   8512
#define DT_OFF  8448
#define DPROJ_PAD 8576
#define ZXH_COLS 8448

#define K1  DMODEL
#define K2  DINNER

// ---------------- scratch ------------------------------------------------------
__device__ __half gZXh[(size_t)TT * ZXH_COLS];
__device__ float  gDtRaw[(size_t)TT * NH];
__device__ __half gXCh[(size_t)TT * CONVDIM];
__device__ float  gYb[(size_t)TT * DINNER];
__device__ __half gStH[(size_t)NBATCH * NCHUNK * NH * HD * DSTATE];  // chunk states -> prefix states (in place)
__device__ float  gDt[TT * NH];
__device__ float  gDalog[TT * NH];
__device__ float  gAsum[NBATCH * NCHUNK * NH];

__device__ __half gA1[(size_t)TT * K1];
__device__ __half gB1[(size_t)DPROJ_PAD * K1];
__device__ __half gA2[(size_t)TT * K2];
__device__ __half gB2[(size_t)DMODEL * K2];

// ================= helpers ======================================================
__device__ __forceinline__ uint32_t smem_u32(const void* p) {
    uint32_t a;
    asm("{ .reg .u64 t; cvta.to.shared.u64 t, %1; cvt.u32.u64 %0, t; }" : "=r"(a) : "l"(p));
    return a;
}
__device__ __forceinline__ void cp16(uint32_t sa, const void* g) {
    asm volatile("cp.async.cg.shared.global [%0], [%1], 16;" :: "r"(sa), "l"(g));
}
__device__ __forceinline__ void ldmx4(uint32_t* r, uint32_t addr) {
    asm volatile("ldmatrix.sync.aligned.m8n8.x4.shared.b16 {%0,%1,%2,%3}, [%4];"
        : "=r"(r[0]), "=r"(r[1]), "=r"(r[2]), "=r"(r[3]) : "r"(addr));
}
__device__ __forceinline__ void mma16816(float* d, const uint32_t* a, const uint32_t* b) {
    asm volatile("mma.sync.aligned.m16n8k16.row.col.f32.f16.f16.f32 "
        "{%0,%1,%2,%3}, {%4,%5,%6,%7}, {%8,%9}, {%0,%1,%2,%3};"
        : "+f"(d[0]), "+f"(d[1]), "+f"(d[2]), "+f"(d[3])
        : "r"(a[0]), "r"(a[1]), "r"(a[2]), "r"(a[3]), "r"(b[0]), "r"(b[1]));
}

// ================= shared GEMM mainloop macro-body ==============================
#define ROWB 80
#define TILE_B (128*ROWB)
#define STAGE_B (2*TILE_B)
#define NSTG 3
#define GM_SMEM (NSTG*STAGE_B)

#define GEMM_MAINLOOP(A_, B_, K_)                                                   \
    extern __shared__ char smem[];                                                 \
    const uint32_t sb = smem_u32(smem);                                            \
    const int tid = threadIdx.x;                                                   \
    const int wid = tid >> 5;                                                      \
    const int lane = tid & 31;                                                     \
    const int m0 = blockIdx.y * 128;                                               \
    const int n0 = blockIdx.x * 128;                                               \
    const int warp_m = wid & 1;                                                    \
    const int warp_n = wid >> 1;                                                   \
    const int NKB = (K_) >> 5;                                                     \
    float acc[4][4][4];                                                            \
    _Pragma("unroll")                                                              \
    for (int mi = 0; mi < 4; mi++)                                                 \
        _Pragma("unroll")                                                          \
        for (int ni = 0; ni < 4; ni++)                                             \
            _Pragma("unroll")                                                      \
            for (int r = 0; r < 4; r++) acc[mi][ni][r] = 0.f;                      \
    const int lrow = tid >> 2;                                                     \
    const int lch  = tid & 3;                                                      \
    auto load_stage = [&](int s, int kb) {                                         \
        uint32_t base = sb + s * STAGE_B;                                          \
        const __half* gA = (A_) + (size_t)m0 * (K_) + (size_t)kb * 32;             \
        const __half* gB = (B_) + (size_t)n0 * (K_) + (size_t)kb * 32;             \
        _Pragma("unroll")                                                          \
        for (int i = 0; i < 2; i++) {                                              \
            int row = lrow + i * 64;                                               \
            cp16(base + row * ROWB + lch * 16, gA + (size_t)row * (K_) + lch * 8); \
        }                                                                          \
        _Pragma("unroll")                                                          \
        for (int i = 0; i < 2; i++) {                                              \
            int row = lrow + i * 64;                                               \
            cp16(base + TILE_B + row * ROWB + lch * 16, gB + (size_t)row * (K_) + lch * 8); \
        }                                                                          \
        asm volatile("cp.async.commit_group;" ::: "memory");                       \
    };                                                                             \
    const int a_r  = lane & 15;                                                    \
    const int a_kq = (lane >> 4) * 8;                                              \
    const int b_n  = ((lane >> 4) << 3) + (lane & 7);                              \
    const int b_kq = ((lane >> 3) & 1) * 8;                                        \
    load_stage(0, 0);                                                              \
    load_stage(1, 1 < NKB ? 1 : 0);                                                \
    for (int kb = 0; kb < NKB; kb++) {                                             \
        const int s = kb % NSTG;                                                   \
        if (kb + 1 < NKB) asm volatile("cp.async.wait_group 1;" ::: "memory");     \
        else              asm volatile("cp.async.wait_group 0;" ::: "memory");     \
        __syncthreads();                                                           \
        if (kb + 2 < NKB) load_stage((kb + 2) % NSTG, kb + 2);                     \
        const uint32_t abase = sb + s * STAGE_B;                                   \
        const uint32_t bbase = abase + TILE_B;                                     \
        _Pragma("unroll")                                                          \
        for (int ks = 0; ks < 2; ks++) {                                           \
            const int k0 = ks * 16;                                                \
            uint32_t af[4][4], bf[2][4];                                           \
            _Pragma("unroll")                                                      \
            for (int mi = 0; mi < 4; mi++) {                                       \
                int m = warp_m * 64 + mi * 16 + a_r;                               \
                ldmx4(af[mi], abase + m * ROWB + (k0 + a_kq) * 2);                 \
            }                                                                      \
            _Pragma("unroll")                                                      \
            for (int ni2 = 0; ni2 < 2; ni2++) {                                    \
                int n = warp_n * 32 + ni2 * 16 + b_n;                              \
                ldmx4(bf[ni2], bbase + n * ROWB + (k0 + b_kq) * 2);                \
            }                                                                      \
            _Pragma("unroll")                                                      \
            for (int mi = 0; mi < 4; mi++)                                         \
                _Pragma("unroll")                                                  \
                for (int ni = 0; ni < 4; ni++)                                     \
                    mma16816(acc[mi][ni], af[mi], &bf[ni >> 1][(ni & 1) * 2]);     \
        }                                                                          \
    }                                                                              \
    const int er = lane >> 2;                                                      \
    const int ec = (lane & 3) * 2;

// ================= GEMM2: fp32 output ===========================================
__global__ __launch_bounds__(256)
void gemm_mma_kernel(const __half* __restrict__ A, const __half* __restrict__ B,
                     float* __restrict__ C, int Nreal, int K)
{
    GEMM_MAINLOOP(A, B, K)
#pragma unroll
    for (int mi = 0; mi < 4; mi++) {
#pragma unroll
        for (int ni = 0; ni < 4; ni++) {
            int col = n0 + warp_n * 32 + ni * 8 + ec;
            if (col < Nreal) {
                int row = m0 + warp_m * 64 + mi * 16 + er;
                float* p0 = C + (size_t)row * Nreal + col;
                p0[0] = acc[mi][ni][0];
                p0[1] = acc[mi][ni][1];
                float* p1 = p0 + (size_t)8 * Nreal;
                p1[0] = acc[mi][ni][2];
                p1[1] = acc[mi][ni][3];
            }
        }
    }
}

// ================= GEMM1: split fp16/fp32 output ================================
__global__ __launch_bounds__(256)
void gemm_mma_h_kernel(const __half* __restrict__ A, const __half* __restrict__ B, int K)
{
    GEMM_MAINLOOP(A, B, K)
#pragma unroll
    for (int mi = 0; mi < 4; mi++) {
#pragma unroll
        for (int ni = 0; ni < 4; ni++) {
            int col = n0 + warp_n * 32 + ni * 8 + ec;
            int row = m0 + warp_m * 64 + mi * 16 + er;
            if (col < DT_OFF) {
                *(__half2*)&gZXh[(size_t)row * ZXH_COLS + col] =
                    __half2(__float2half_rn(acc[mi][ni][0]), __float2half_rn(acc[mi][ni][1]));
                *(__half2*)&gZXh[(size_t)(row + 8) * ZXH_COLS + col] =
                    __half2(__float2half_rn(acc[mi][ni][2]), __float2half_rn(acc[mi][ni][3]));
            } else if (col < DPROJ) {
                int dc = col - DT_OFF;
                gDtRaw[(size_t)row * NH + dc]           = acc[mi][ni][0];
                gDtRaw[(size_t)row * NH + dc + 1]       = acc[mi][ni][1];
                gDtRaw[(size_t)(row + 8) * NH + dc]     = acc[mi][ni][2];
                gDtRaw[(size_t)(row + 8) * NH + dc + 1] = acc[mi][ni][3];
            }
        }
    }
}

// ================= fp32 -> fp16 convert ========================================
__global__ __launch_bounds__(256)
void convert_kernel(const float* __restrict__ src, __half* __restrict__ dst,
                    size_t n_src, size_t n_dst)
{
    size_t i = (size_t)blockIdx.x * blockDim.x + threadIdx.x;
    if (i >= n_dst) return;
    float x = (i < n_src) ? src[i] : 0.f;
    dst[i] = __float2half_rn(x);
}

// ================= pointwise ====================================================
__global__ __launch_bounds__(256)
void dt_kernel(const float* __restrict__ dt_bias, const float* __restrict__ A_log)
{
    int i = blockIdx.x * blockDim.x + threadIdx.x;
    if (i >= TT * NH) return;
    int h = i & (NH - 1);
    float x = gDtRaw[i] + dt_bias[h];
    float sp = (x > 20.f) ? x : log1pf(__expf(x));
    float A = -__expf(A_log[h]);
    gDt[i] = sp;
    gDalog[i] = sp * A;
}

// ================= conv1d: sliding window, fp16 in/out ==========================
__global__ __launch_bounds__(256)
void conv_kernel(const float* __restrict__ conv_w, const float* __restrict__ conv_b)
{
    const int per_tok = CONVDIM / 4;
    int idx = blockIdx.x * blockDim.x + threadIdx.x;
    if (idx >= (TT / 8) * per_tok) return;
    int tb = idx / per_tok;
    int c4 = (idx - tb * per_tok) * 4;
    int t0 = tb * 8;

    float wk[4][4], bb[4];
#pragma unroll
    for (int j = 0; j < 4; j++) {
        bb[j] = conv_b[c4 + j];
#pragma unroll
        for (int k = 0; k < 4; k++) wk[j][k] = conv_w[(c4 + j) * DCONV + k];
    }

    auto ldrow = [&](int t) {
        const __half* p = &gZXh[(size_t)t * ZXH_COLS + DINNER + c4];
        __half2 a = *(const __half2*)(p);
        __half2 b = *(const __half2*)(p + 2);
        return make_float4(__low2float(a), __high2float(a), __low2float(b), __high2float(b));
    };

    float4 rm3, rm2, rm1;
    if ((t0 & (LSEQ - 1)) == 0) {
        rm3 = make_float4(0.f, 0.f, 0.f, 0.f);
        rm2 = rm3; rm1 = rm3;
    } else {
        rm3 = ldrow(t0 - 3); rm2 = ldrow(t0 - 2); rm1 = ldrow(t0 - 1);
    }

#pragma unroll
    for (int i = 0; i < 8; i++) {
        int t = t0 + i;
        float4 cur = ldrow(t);
        float a0 = bb[0] + rm3.x * wk[0][0] + rm2.x * wk[0][1] + rm1.x * wk[0][2] + cur.x * wk[0][3];
        float a1 = bb[1] + rm3.y * wk[1][0] + rm2.y * wk[1][1] + rm1.y * wk[1][2] + cur.y * wk[1][3];
        float a2 = bb[2] + rm3.z * wk[2][0] + rm2.z * wk[2][1] + rm1.z * wk[2][2] + cur.z * wk[2][3];
        float a3 = bb[3] + rm3.w * wk[3][0] + rm2.w * wk[3][1] + rm1.w * wk[3][2] + cur.w * wk[3][3];
        a0 = a0 / (1.f + __expf(-a0));
        a1 = a1 / (1.f + __expf(-a1));
        a2 = a2 / (1.f + __expf(-a2));
        a3 = a3 / (1.f + __expf(-a3));
        __half* o = &gXCh[(size_t)t * CONVDIM + c4];
        *(__half2*)(o)     = __half2(__float2half_rn(a0), __float2half_rn(a1));
        *(__half2*)(o + 2) = __half2(__float2half_rn(a2), __float2half_rn(a3));
        rm3 = rm2; rm2 = rm1; rm1 = cur;
    }
}

// ================= states kernel: MMA3 only, fp16 output ========================
#define SA_LDN 72
#define SA_XDT 0
#define SA_BT  (64*SA_LDN)
#define SA_HALVES (SA_BT + 128*SA_LDN)       // 13824 halves
#define SA_ACS (SA_HALVES*2)                 // 27648 bytes
#define SA_SMEM (SA_ACS + 128*4)

__global__ __launch_bounds__(256)
void states_kernel()
{
    extern __shared__ char ssm[];
    __half* H   = (__half*)ssm;
    float* sAcs = (float*)(ssm + SA_ACS);
    float* sDec = sAcs + 64;
    __half* sStg = (__half*)ssm;             // fp16 staging overlay [64][136]
    const uint32_t sb = smem_u32(ssm);

    const int bc = blockIdx.x;
    const int h  = blockIdx.y;
    const int tid = threadIdx.x;
    const int wid = tid >> 5;
    const int lane = tid & 31;
    const int t0 = bc * CHUNKSZ;

    if (tid < 64) sAcs[tid] = gDalog[(size_t)(t0 + tid) * NH + h];
    __syncthreads();
    if (tid == 0) {
        float s = 0.f;
        for (int l = 0; l < 64; l++) { s += sAcs[l]; sAcs[l] = s; }
    }
    __syncthreads();
    if (tid < 64) sDec[tid] = __expf(sAcs[63] - sAcs[tid]);
    __syncthreads();

    // B transposed
    for (int i = tid; i < 2048; i += 256) {
        int s  = i & 63;
        int c4 = (i >> 6) << 2;
        const __half* row = &gXCh[(size_t)(t0 + s) * CONVDIM + DINNER];
        __half2 b01 = *(const __half2*)(row + c4);
        __half2 b23 = *(const __half2*)(row + c4 + 2);
        H[SA_BT + (c4 + 0) * SA_LDN + s] = __low2half(b01);
        H[SA_BT + (c4 + 1) * SA_LDN + s] = __high2half(b01);
        H[SA_BT + (c4 + 2) * SA_LDN + s] = __low2half(b23);
        H[SA_BT + (c4 + 3) * SA_LDN + s] = __high2half(b23);
    }
    // X * dt * dec transposed
    for (int i = tid; i < 1024; i += 256) {
        int s  = i & 63;
        int c4 = (i >> 6) << 2;
        float dd = gDt[(size_t)(t0 + s) * NH + h] * sDec[s];
        const __half* row = &gXCh[(size_t)(t0 + s) * CONVDIM + h * HD];
        __half2 x01 = *(const __half2*)(row + c4);
        __half2 x23 = *(const __half2*)(row + c4 + 2);
        H[SA_XDT + (c4 + 0) * SA_LDN + s] = __float2half_rn(__low2float(x01) * dd);
        H[SA_XDT + (c4 + 1) * SA_LDN + s] = __float2half_rn(__high2float(x01) * dd);
        H[SA_XDT + (c4 + 2) * SA_LDN + s] = __float2half_rn(__low2float(x23) * dd);
        H[SA_XDT + (c4 + 3) * SA_LDN + s] = __float2half_rn(__high2float(x23) * dd);
    }
    __syncthreads();

    const int a_r  = lane & 15;
    const int a_kq = (lane >> 4) * 8;
    const int b_n  = ((lane >> 4) << 3) + (lane & 7);
    const int b_kq = ((lane >> 3) & 1) * 8;
    const int er = lane >> 2;
    const int ec = (lane & 3) * 2;

    // S[p][n] = sum_s Xdt[p,s] * Bt[n,s]; warps 2(p) x 4(n)
    float acc3[2][4][4];
    const int warp_p = wid & 1;
    const int warp_n = wid >> 1;
#pragma unroll
    for (int mi = 0; mi < 2; mi++)
#pragma unroll
        for (int ni = 0; ni < 4; ni++)
#pragma unroll
            for (int r = 0; r < 4; r++) acc3[mi][ni][r] = 0.f;
#pragma unroll
    for (int kk = 0; kk < 4; kk++) {
        const int k0 = kk * 16;
        uint32_t af[2][4], bf[2][4];
#pragma unroll
        for (int mi = 0; mi < 2; mi++) {
            int p = warp_p * 32 + mi * 16 + a_r;
            ldmx4(af[mi], sb + (SA_XDT + p * SA_LDN) * 2 + (k0 + a_kq) * 2);
        }
#pragma unroll
        for (int ni2 = 0; ni2 < 2; ni2++) {
            int n = warp_n * 32 + ni2 * 16 + b_n;
            ldmx4(bf[ni2], sb + (SA_BT + n * SA_LDN) * 2 + (k0 + b_kq) * 2);
        }
#pragma unroll
        for (int mi = 0; mi < 2; mi++)
#pragma unroll
            for (int ni = 0; ni < 4; ni++)
                mma16816(acc3[mi][ni], af[mi], &bf[ni >> 1][(ni & 1) * 2]);
    }
    __syncthreads();

    // stage fp16, write coalesced
#pragma unroll
    for (int mi = 0; mi < 2; mi++)
#pragma unroll
        for (int ni = 0; ni < 4; ni++)
#pragma unroll
            for (int r = 0; r < 4; r += 2) {
                int p = warp_p * 32 + mi * 16 + (r >> 1) * 8 + er;
                int n = warp_n * 32 + ni * 8 + ec;
                *(__half2*)&sStg[p * 136 + n] =
                    __half2(__float2half_rn(acc3[mi][ni][r]), __float2half_rn(acc3[mi][ni][r + 1]));
            }
    __syncthreads();
    {
        size_t base = ((size_t)bc * NH + h) * (HD * DSTATE);
        for (int i = tid; i < 2048; i += 256) {
            int p  = i >> 5;
            int c4 = (i & 31) << 2;
            *(uint2*)&gStH[base + (size_t)p * DSTATE + c4] = *(const uint2*)&sStg[p * 136 + c4];
        }
    }

    if (tid == 0) gAsum[bc * NH + h] = sAcs[63];
}

// ================= inter-chunk scan: fp16 in/out, fp32 accum ====================
__global__ __launch_bounds__(512)
void scan_kernel()
{
    const int bh = blockIdx.x;
    const int b = bh >> 6, h = bh & 63;
    const int tid = threadIdx.x;
    const int off = tid * 16;

    float prev[16];
#pragma unroll
    for (int q = 0; q < 16; q++) prev[q] = 0.f;

    for (int c = 0; c < NCHUNK; c++) {
        int bc = b * NCHUNK + c;
        size_t base = ((size_t)bc * NH + h) * (HD * DSTATE) + off;
        float dec = __expf(gAsum[bc * NH + h]);
        __half2 cur[8];
#pragma unroll
        for (int q = 0; q < 8; q++) cur[q] = *(__half2*)&gStH[base + q * 2];
#pragma unroll
        for (int q = 0; q < 8; q++)
            *(__half2*)&gStH[base + q * 2] =
                __half2(__float2half_rn(prev[q * 2]), __float2half_rn(prev[q * 2 + 1]));
#pragma unroll
        for (int q = 0; q < 8; q++) {
            prev[q * 2]     = prev[q * 2]     * dec + __low2float(cur[q]);
            prev[q * 2 + 1] = prev[q * 2 + 1] * dec + __high2float(cur[q]);
        }
    }
}

// ================= output kernel: M + Y_diag + Y_off + skip + gate ==============
#define SB_LDW 136
#define SB_LDN 72
#define SB_B   0
#define SB_C   (64*SB_LDW)
#define SB_CS  (2*64*SB_LDW)
#define SB_ST  (3*64*SB_LDW)
#define SB_XT  (4*64*SB_LDW)
#define SB_M   (SB_XT + 64*SB_LDN)
#define SB_HALVES (SB_M + 64*SB_LDN)          // 44032 halves
#define SB_ACS (SB_HALVES*2)                  // 88064 bytes
#define SB_SMEM (SB_ACS + 64*4)

__global__ __launch_bounds__(256)
void output_kernel(const float* __restrict__ Dparam)
{
    extern __shared__ char osm[];
    __half* H   = (__half*)osm;
    float* sAcs = (float*)(osm + SB_ACS);
    float* sYf  = (float*)osm;                // fp32 Y staging overlay (over SB_B)
    const uint32_t sb = smem_u32(osm);

    const int bc = blockIdx.x;
    const int h  = blockIdx.y;
    const int tid = threadIdx.x;
    const int wid = tid >> 5;
    const int lane = tid & 31;
    const int t0 = bc * CHUNKSZ;

    if (tid < 64) sAcs[tid] = gDalog[(size_t)(t0 + tid) * NH + h];
    __syncthreads();
    if (tid == 0) {
        float s = 0.f;
        for (int l = 0; l < 64; l++) { s += sAcs[l]; sAcs[l] = s; }
    }
    __syncthreads();

    // load B, C, Cs = C*exp(acs), St
    for (int i = tid; i < 2048; i += 256) {
        int s  = i & 63;
        int c4 = (i >> 6) << 2;
        const __half* row = &gXCh[(size_t)(t0 + s) * CONVDIM + DINNER];
        *(__half2*)&H[SB_B + s * SB_LDW + c4]     = *(const __half2*)(row + c4);
        *(__half2*)&H[SB_B + s * SB_LDW + c4 + 2] = *(const __half2*)(row + c4 + 2);
        __half2 c01 = *(const __half2*)(row + DSTATE + c4);
        __half2 c23 = *(const __half2*)(row + DSTATE + c4 + 2);
        *(__half2*)&H[SB_C + s * SB_LDW + c4]     = c01;
        *(__half2*)&H[SB_C + s * SB_LDW + c4 + 2] = c23;
        float sdo = __expf(sAcs[s]);
        *(__half2*)&H[SB_CS + s * SB_LDW + c4] =
            __half2(__float2half_rn(__low2float(c01) * sdo), __float2half_rn(__high2float(c01) * sdo));
        *(__half2*)&H[SB_CS + s * SB_LDW + c4 + 2] =
            __half2(__float2half_rn(__low2float(c23) * sdo), __float2half_rn(__high2float(c23) * sdo));
        const __half* srow = &gStH[(((size_t)bc * NH + h) * HD + s) * DSTATE];
        *(__half2*)&H[SB_ST + s * SB_LDW + c4]     = *(const __half2*)(srow + c4);
        *(__half2*)&H[SB_ST + s * SB_LDW + c4 + 2] = *(const __half2*)(srow + c4 + 2);
    }
    // Xt = (x*dt) transposed
    for (int i = tid; i < 1024; i += 256) {
        int s  = i & 63;
        int c4 = (i >> 6) << 2;
        float d = gDt[(size_t)(t0 + s) * NH + h];
        const __half* row = &gXCh[(size_t)(t0 + s) * CONVDIM + h * HD];
        __half2 x01 = *(const __half2*)(row + c4);
        __half2 x23 = *(const __half2*)(row + c4 + 2);
        H[SB_XT + (c4 + 0) * SB_LDN + s] = __float2half_rn(__low2float(x01) * d);
        H[SB_XT + (c4 + 1) * SB_LDN + s] = __float2half_rn(__high2float(x01) * d);
        H[SB_XT + (c4 + 2) * SB_LDN + s] = __float2half_rn(__low2float(x23) * d);
        H[SB_XT + (c4 + 3) * SB_LDN + s] = __float2half_rn(__high2float(x23) * d);
    }
    __syncthreads();

    const int a_r  = lane & 15;
    const int a_kq = (lane >> 4) * 8;
    const int b_n  = ((lane >> 4) << 3) + (lane & 7);
    const int b_kq = ((lane >> 3) & 1) * 8;
    const int er = lane >> 2;
    const int ec = (lane & 3) * 2;

    // MMA_M: M[l][s] = sum_n C[l,n]*B[s,n]; warps 4(l) x 2(s); mask*exp -> M16
    {
        const int warp_l = wid & 3;
        const int warp_s = wid >> 2;
        float acc[4][4];
#pragma unroll
        for (int ni = 0; ni < 4; ni++)
#pragma unroll
            for (int r = 0; r < 4; r++) acc[ni][r] = 0.f;
#pragma unroll
        for (int kk = 0; kk < 8; kk++) {
            const int k0 = kk * 16;
            uint32_t af[4], bf[2][4];
            ldmx4(af, sb + (SB_C + (warp_l * 16 + a_r) * SB_LDW) * 2 + (k0 + a_kq) * 2);
#pragma unroll
            for (int ni2 = 0; ni2 < 2; ni2++) {
                int s = warp_s * 32 + ni2 * 16 + b_n;
                ldmx4(bf[ni2], sb + (SB_B + s * SB_LDW) * 2 + (k0 + b_kq) * 2);
            }
#pragma unroll
            for (int ni = 0; ni < 4; ni++)
                mma16816(acc[ni], af, &bf[ni >> 1][(ni & 1) * 2]);
        }
#pragma unroll
        for (int ni = 0; ni < 4; ni++) {
#pragma unroll
            for (int r = 0; r < 4; r++) {
                int l = warp_l * 16 + (r >> 1) * 8 + er;
                int s = warp_s * 32 + ni * 8 + ec + (r & 1);
                float v = (s <= l) ? acc[ni][r] * __expf(sAcs[l] - sAcs[s]) : 0.f;
                H[SB_M + l * SB_LDN + s] = __float2half_rn(v);
            }
        }
    }
    __syncthreads();

    // MMA_O + MMA_D: Y[l][p] = sum_n Cs[l,n]*St[p,n] + sum_s M[l,s]*Xt[p,s]
    float accY[4][4];
    {
        const int warp_l = wid & 3;
        const int warp_p = wid >> 2;
#pragma unroll
        for (int ni = 0; ni < 4; ni++)
#pragma unroll
            for (int r = 0; r < 4; r++) accY[ni][r] = 0.f;
#pragma unroll
        for (int kk = 0; kk < 8; kk++) {
            const int k0 = kk * 16;
            uint32_t af[4], bf[2][4];
            ldmx4(af, sb + (SB_CS + (warp_l * 16 + a_r) * SB_LDW) * 2 + (k0 + a_kq) * 2);
#pragma unroll
            for (int ni2 = 0; ni2 < 2; ni2++) {
                int p = warp_p * 32 + ni2 * 16 + b_n;
                ldmx4(bf[ni2], sb + (SB_ST + p * SB_LDW) * 2 + (k0 + b_kq) * 2);
            }
#pragma unroll
            for (int ni = 0; ni < 4; ni++)
                mma16816(accY[ni], af, &bf[ni >> 1][(ni & 1) * 2]);
        }
#pragma unroll
        for (int kk = 0; kk < 4; kk++) {
            const int k0 = kk * 16;
            uint32_t af[4], bf[2][4];
            ldmx4(af, sb + (SB_M + (warp_l * 16 + a_r) * SB_LDN) * 2 + (k0 + a_kq) * 2);
#pragma unroll
            for (int ni2 = 0; ni2 < 2; ni2++) {
                int p = warp_p * 32 + ni2 * 16 + b_n;
                ldmx4(bf[ni2], sb + (SB_XT + p * SB_LDN) * 2 + (k0 + b_kq) * 2);
            }
#pragma unroll
            for (int ni = 0; ni < 4; ni++)
                mma16816(accY[ni], af, &bf[ni >> 1][(ni & 1) * 2]);
        }
    }
    __syncthreads();

    // stage Y fp32 over SB_B region
    {
        const int warp_l = wid & 3;
        const int warp_p = wid >> 2;
#pragma unroll
        for (int ni = 0; ni < 4; ni++)
#pragma unroll
            for (int r = 0; r < 4; r++) {
                int l = warp_l * 16 + (r >> 1) * 8 + er;
                int p = warp_p * 32 + ni * 8 + ec + (r & 1);
                sYf[l * 68 + p] = accY[ni][r];
            }
    }
    __syncthreads();

    // epilogue: y = Y + x*D, gated by silu(z)
    const int tx = tid & 15;
    const int ty = tid >> 4;
    const float Dh = Dparam[h];
#pragma unroll
    for (int i = 0; i < 4; i++) {
        int l = ty * 4 + i;
        size_t tz = (size_t)(t0 + l);
        float4 m4 = *(const float4*)&sYf[l * 68 + tx * 4];
        const __half* xrow = &gXCh[tz * CONVDIM + h * HD + tx * 4];
        __half2 xa = *(const __half2*)(xrow);
        __half2 xb = *(const __half2*)(xrow + 2);
        const __half* zrow = &gZXh[tz * ZXH_COLS + h * HD + tx * 4];
        __half2 za = *(const __half2*)(zrow);
        __half2 zb = *(const __half2*)(zrow + 2);
        float z0 = __low2float(za), z1 = __high2float(za);
        float z2 = __low2float(zb), z3 = __high2float(zb);
        float4 y4;
        y4.x = (m4.x + __low2float(xa)  * Dh) * (z0 / (1.f + __expf(-z0)));
        y4.y = (m4.y + __high2float(xa) * Dh) * (z1 / (1.f + __expf(-z1)));
        y4.z = (m4.z + __low2float(xb)  * Dh) * (z2 / (1.f + __expf(-z2)));
        y4.w = (m4.w + __high2float(xb) * Dh) * (z3 / (1.f + __expf(-z3)));
        *(float4*)&gYb[tz * DINNER + h * HD + tx * 4] = y4;
    }
}

// ================= fused RMSNorm + fp16 convert =================================
__global__ __launch_bounds__(256)
void rms_convert_kernel(const float* __restrict__ norm_w, __half* __restrict__ dst)
{
    const int t = blockIdx.x;
    const int tid = threadIdx.x;
    const float* y = &gYb[(size_t)t * DINNER];

    float ss = 0.f;
    for (int i = tid * 4; i < DINNER; i += 256 * 4) {
        float4 v = *(const float4*)(y + i);
        ss += v.x * v.x + v.y * v.y + v.z * v.z + v.w * v.w;
    }
#pragma unroll
    for (int o = 16; o > 0; o >>= 1) ss += __shfl_down_sync(0xffffffffu, ss, o);

    __shared__ float red[8];
    if ((tid & 31) == 0) red[tid >> 5] = ss;
    __syncthreads();
    if (tid == 0) {
        float tot = 0.f;
#pragma unroll
        for (int w = 0; w < 8; w++) tot += red[w];
        red[0] = rsqrtf(tot / (float)DINNER + 1e-5f);
    }
    __syncthreads();
    const float scale = red[0];

    __half* d0 = dst + (size_t)t * DINNER;
    for (int i = tid * 4; i < DINNER; i += 256 * 4) {
        float4 v = *(const float4*)(y + i);
        float4 w = *(const float4*)(norm_w + i);
        __half2 hA = __half2(__float2half_rn(v.x * scale * w.x),
                             __float2half_rn(v.y * scale * w.y));
        __half2 hB = __half2(__float2half_rn(v.z * scale * w.z),
                             __float2half_rn(v.w * scale * w.w));
        *(__half2*)(d0 + i)     = hA;
        *(__half2*)(d0 + i + 2) = hB;
    }
}

// ================= launch =======================================================
extern "C" void kernel_launch(void* const* d_in, const int* in_sizes, int n_in,
                              void* d_out, int out_size)
{
    const float* u       = (const float*)d_in[0];
    const float* W_in    = (const float*)d_in[1];
    const float* conv_w  = (const float*)d_in[2];
    const float* conv_b  = (const float*)d_in[3];
    const float* dt_bias = (const float*)d_in[4];
    const float* A_log   = (const float*)d_in[5];
    const float* Dparam  = (const float*)d_in[6];
    const float* norm_w  = (const float*)d_in[7];
    const float* W_out   = (const float*)d_in[8];
    float* out = (float*)d_out;

    void *pA1, *pB1, *pA2, *pB2;
    cudaGetSymbolAddress(&pA1, gA1);
    cudaGetSymbolAddress(&pB1, gB1);
    cudaGetSymbolAddress(&pA2, gA2);
    cudaGetSymbolAddress(&pB2, gB2);

    cudaFuncSetAttribute(states_kernel, cudaFuncAttributeMaxDynamicSharedMemorySize, SA_SMEM);
    cudaFuncSetAttribute(output_kernel, cudaFuncAttributeMaxDynamicSharedMemorySize, SB_SMEM);
    cudaFuncSetAttribute(gemm_mma_kernel,   cudaFuncAttributeMaxDynamicSharedMemorySize, GM_SMEM);
    cudaFuncSetAttribute(gemm_mma_h_kernel, cudaFuncAttributeMaxDynamicSharedMemorySize, GM_SMEM);

    convert_kernel<<<(int)(((size_t)TT * K1 + 255) / 256), 256>>>(
        u, (__half*)pA1, (size_t)TT * K1, (size_t)TT * K1);
    convert_kernel<<<(int)(((size_t)DPROJ_PAD * K1 + 255) / 256), 256>>>(
        W_in, (__half*)pB1, (size_t)DPROJ * K1, (size_t)DPROJ_PAD * K1);
    convert_kernel<<<(int)(((size_t)DMODEL * K2 + 255) / 256), 256>>>(
        W_out, (__half*)pB2, (size_t)DMODEL * K2, (size_t)DMODEL * K2);

    // idx 3: in-projection
    {
        dim3 grid(DPROJ_PAD / 128, TT / 128);
        gemm_mma_h_kernel<<<grid, 256, GM_SMEM>>>((const __half*)pA1, (const __half*)pB1, K1);
    }
    dt_kernel<<<(TT * NH + 255) / 256, 256>>>(dt_bias, A_log);
    conv_kernel<<<((TT / 8) * (CONVDIM / 4) + 255) / 256, 256>>>(conv_w, conv_b);
    {
        dim3 grid(NBATCH * NCHUNK, NH);
        states_kernel<<<grid, 256, SA_SMEM>>>();
    }
    scan_kernel<<<NBATCH * NH, 512>>>();
    {
        dim3 grid(NBATCH * NCHUNK, NH);
        output_kernel<<<grid, 256, SB_SMEM>>>(Dparam);
    }
    rms_convert_kernel<<<TT, 256>>>(norm_w, (__half*)pA2);
    {
        dim3 grid(DMODEL / 128, TT / 128);
        gemm_mma_kernel<<<grid, 256, GM_SMEM>>>((const __half*)pA2, (const __half*)pB2,
                                                out, DMODEL, K2);
    }
}

// round 17
// speedup vs baseline: 1.1197x; 1.1197x over previous
#include <cuda_runtime.h>
#include <cuda_fp16.h>
#include <cstdint>
#include <math.h>

#define TT      8192
#define LSEQ    4096
#define NBATCH  2
#define DMODEL  2048
#define DINNER  4096
#define DSTATE  128
#define DCONV   4
#define NH      64
#define HD      64
#define CHUNKSZ 64
#define NCHUNK  64
#define CONVDIM 4352
#define DPROJ   8512
#define DT_OFF  8448
#define DPROJ_PAD 8576
#define ZXH_COLS 8448

#define K1  DMODEL
#define K2  DINNER

// ---------------- scratch ------------------------------------------------------
__device__ __half gZXh[(size_t)TT * ZXH_COLS];
__device__ float  gDtRaw[(size_t)TT * NH];
__device__ __half gXCh[(size_t)TT * CONVDIM];
__device__ float  gYb[(size_t)TT * DINNER];
__device__ __half gStH[(size_t)NBATCH * NCHUNK * NH * HD * DSTATE]; // chunk -> prefix (in place)
__device__ float  gDt[TT * NH];
__device__ float  gDalog[TT * NH];
__device__ float  gAsum[NBATCH * NCHUNK * NH];

__device__ __half gA1[(size_t)TT * K1];
__device__ __half gB1[(size_t)DPROJ_PAD * K1];
__device__ __half gA2[(size_t)TT * K2];
__device__ __half gB2[(size_t)DMODEL * K2];

// ================= helpers ======================================================
__device__ __forceinline__ uint32_t smem_u32(const void* p) {
    uint32_t a;
    asm("{ .reg .u64 t; cvta.to.shared.u64 t, %1; cvt.u32.u64 %0, t; }" : "=r"(a) : "l"(p));
    return a;
}
__device__ __forceinline__ void cp16(uint32_t sa, const void* g) {
    asm volatile("cp.async.cg.shared.global [%0], [%1], 16;" :: "r"(sa), "l"(g));
}
__device__ __forceinline__ void ldmx4(uint32_t* r, uint32_t addr) {
    asm volatile("ldmatrix.sync.aligned.m8n8.x4.shared.b16 {%0,%1,%2,%3}, [%4];"
        : "=r"(r[0]), "=r"(r[1]), "=r"(r[2]), "=r"(r[3]) : "r"(addr));
}
__device__ __forceinline__ void mma16816(float* d, const uint32_t* a, const uint32_t* b) {
    asm volatile("mma.sync.aligned.m16n8k16.row.col.f32.f16.f16.f32 "
        "{%0,%1,%2,%3}, {%4,%5,%6,%7}, {%8,%9}, {%0,%1,%2,%3};"
        : "+f"(d[0]), "+f"(d[1]), "+f"(d[2]), "+f"(d[3])
        : "r"(a[0]), "r"(a[1]), "r"(a[2]), "r"(a[3]), "r"(b[0]), "r"(b[1]));
}

// ================= shared GEMM mainloop macro-body ==============================
#define ROWB 80
#define TILE_B (128*ROWB)
#define STAGE_B (2*TILE_B)
#define NSTG 3
#define GM_SMEM (NSTG*STAGE_B)

#define GEMM_MAINLOOP(A_, B_, K_)                                                   \
    extern __shared__ char smem[];                                                 \
    const uint32_t sb = smem_u32(smem);                                            \
    const int tid = threadIdx.x;                                                   \
    const int wid = tid >> 5;                                                      \
    const int lane = tid & 31;                                                     \
    const int m0 = blockIdx.y * 128;                                               \
    const int n0 = blockIdx.x * 128;                                               \
    const int warp_m = wid & 1;                                                    \
    const int warp_n = wid >> 1;                                                   \
    const int NKB = (K_) >> 5;                                                     \
    float acc[4][4][4];                                                            \
    _Pragma("unroll")                                                              \
    for (int mi = 0; mi < 4; mi++)                                                 \
        _Pragma("unroll")                                                          \
        for (int ni = 0; ni < 4; ni++)                                             \
            _Pragma("unroll")                                                      \
            for (int r = 0; r < 4; r++) acc[mi][ni][r] = 0.f;                      \
    const int lrow = tid >> 2;                                                     \
    const int lch  = tid & 3;                                                      \
    auto load_stage = [&](int s, int kb) {                                         \
        uint32_t base = sb + s * STAGE_B;                                          \
        const __half* gA = (A_) + (size_t)m0 * (K_) + (size_t)kb * 32;             \
        const __half* gB = (B_) + (size_t)n0 * (K_) + (size_t)kb * 32;             \
        _Pragma("unroll")                                                          \
        for (int i = 0; i < 2; i++) {                                              \
            int row = lrow + i * 64;                                               \
            cp16(base + row * ROWB + lch * 16, gA + (size_t)row * (K_) + lch * 8); \
        }                                                                          \
        _Pragma("unroll")                                                          \
        for (int i = 0; i < 2; i++) {                                              \
            int row = lrow + i * 64;                                               \
            cp16(base + TILE_B + row * ROWB + lch * 16, gB + (size_t)row * (K_) + lch * 8); \
        }                                                                          \
        asm volatile("cp.async.commit_group;" ::: "memory");                       \
    };                                                                             \
    const int a_r  = lane & 15;                                                    \
    const int a_kq = (lane >> 4) * 8;                                              \
    const int b_n  = ((lane >> 4) << 3) + (lane & 7);                              \
    const int b_kq = ((lane >> 3) & 1) * 8;                                        \
    load_stage(0, 0);                                                              \
    load_stage(1, 1 < NKB ? 1 : 0);                                                \
    for (int kb = 0; kb < NKB; kb++) {                                             \
        const int s = kb % NSTG;                                                   \
        if (kb + 1 < NKB) asm volatile("cp.async.wait_group 1;" ::: "memory");     \
        else              asm volatile("cp.async.wait_group 0;" ::: "memory");     \
        __syncthreads();                                                           \
        if (kb + 2 < NKB) load_stage((kb + 2) % NSTG, kb + 2);                     \
        const uint32_t abase = sb + s * STAGE_B;                                   \
        const uint32_t bbase = abase + TILE_B;                                     \
        _Pragma("unroll")                                                          \
        for (int ks = 0; ks < 2; ks++) {                                           \
            const int k0 = ks * 16;                                                \
            uint32_t af[4][4], bf[2][4];                                           \
            _Pragma("unroll")                                                      \
            for (int mi = 0; mi < 4; mi++) {                                       \
                int m = warp_m * 64 + mi * 16 + a_r;                               \
                ldmx4(af[mi], abase + m * ROWB + (k0 + a_kq) * 2);                 \
            }                                                                      \
            _Pragma("unroll")                                                      \
            for (int ni2 = 0; ni2 < 2; ni2++) {                                    \
                int n = warp_n * 32 + ni2 * 16 + b_n;                              \
                ldmx4(bf[ni2], bbase + n * ROWB + (k0 + b_kq) * 2);                \
            }                                                                      \
            _Pragma("unroll")                                                      \
            for (int mi = 0; mi < 4; mi++)                                         \
                _Pragma("unroll")                                                  \
                for (int ni = 0; ni < 4; ni++)                                     \
                    mma16816(acc[mi][ni], af[mi], &bf[ni >> 1][(ni & 1) * 2]);     \
        }                                                                          \
    }                                                                              \
    const int er = lane >> 2;                                                      \
    const int ec = (lane & 3) * 2;

// ================= GEMM2: fp32 output ===========================================
__global__ __launch_bounds__(256)
void gemm_mma_kernel(const __half* __restrict__ A, const __half* __restrict__ B,
                     float* __restrict__ C, int Nreal, int K)
{
    GEMM_MAINLOOP(A, B, K)
#pragma unroll
    for (int mi = 0; mi < 4; mi++) {
#pragma unroll
        for (int ni = 0; ni < 4; ni++) {
            int col = n0 + warp_n * 32 + ni * 8 + ec;
            if (col < Nreal) {
                int row = m0 + warp_m * 64 + mi * 16 + er;
                float* p0 = C + (size_t)row * Nreal + col;
                p0[0] = acc[mi][ni][0];
                p0[1] = acc[mi][ni][1];
                float* p1 = p0 + (size_t)8 * Nreal;
                p1[0] = acc[mi][ni][2];
                p1[1] = acc[mi][ni][3];
            }
        }
    }
}

// ================= GEMM1: split fp16/fp32 output ================================
__global__ __launch_bounds__(256)
void gemm_mma_h_kernel(const __half* __restrict__ A, const __half* __restrict__ B, int K)
{
    GEMM_MAINLOOP(A, B, K)
#pragma unroll
    for (int mi = 0; mi < 4; mi++) {
#pragma unroll
        for (int ni = 0; ni < 4; ni++) {
            int col = n0 + warp_n * 32 + ni * 8 + ec;
            int row = m0 + warp_m * 64 + mi * 16 + er;
            if (col < DT_OFF) {
                *(__half2*)&gZXh[(size_t)row * ZXH_COLS + col] =
                    __half2(__float2half_rn(acc[mi][ni][0]), __float2half_rn(acc[mi][ni][1]));
                *(__half2*)&gZXh[(size_t)(row + 8) * ZXH_COLS + col] =
                    __half2(__float2half_rn(acc[mi][ni][2]), __float2half_rn(acc[mi][ni][3]));
            } else if (col < DPROJ) {
                int dc = col - DT_OFF;
                gDtRaw[(size_t)row * NH + dc]           = acc[mi][ni][0];
                gDtRaw[(size_t)row * NH + dc + 1]       = acc[mi][ni][1];
                gDtRaw[(size_t)(row + 8) * NH + dc]     = acc[mi][ni][2];
                gDtRaw[(size_t)(row + 8) * NH + dc + 1] = acc[mi][ni][3];
            }
        }
    }
}

// ================= fp32 -> fp16 convert ========================================
__global__ __launch_bounds__(256)
void convert_kernel(const float* __restrict__ src, __half* __restrict__ dst,
                    size_t n_src, size_t n_dst)
{
    size_t i = (size_t)blockIdx.x * blockDim.x + threadIdx.x;
    if (i >= n_dst) return;
    float x = (i < n_src) ? src[i] : 0.f;
    dst[i] = __float2half_rn(x);
}

// ================= pointwise ====================================================
__global__ __launch_bounds__(256)
void dt_kernel(const float* __restrict__ dt_bias, const float* __restrict__ A_log)
{
    int i = blockIdx.x * blockDim.x + threadIdx.x;
    if (i >= TT * NH) return;
    int h = i & (NH - 1);
    float x = gDtRaw[i] + dt_bias[h];
    float sp = (x > 20.f) ? x : log1pf(__expf(x));
    float A = -__expf(A_log[h]);
    gDt[i] = sp;
    gDalog[i] = sp * A;
}

// ================= conv1d: sliding window, fp16 in/out ==========================
__global__ __launch_bounds__(256)
void conv_kernel(const float* __restrict__ conv_w, const float* __restrict__ conv_b)
{
    const int per_tok = CONVDIM / 4;
    int idx = blockIdx.x * blockDim.x + threadIdx.x;
    if (idx >= (TT / 8) * per_tok) return;
    int tb = idx / per_tok;
    int c4 = (idx - tb * per_tok) * 4;
    int t0 = tb * 8;

    float wk[4][4], bb[4];
#pragma unroll
    for (int j = 0; j < 4; j++) {
        bb[j] = conv_b[c4 + j];
#pragma unroll
        for (int k = 0; k < 4; k++) wk[j][k] = conv_w[(c4 + j) * DCONV + k];
    }

    auto ldrow = [&](int t) {
        const __half* p = &gZXh[(size_t)t * ZXH_COLS + DINNER + c4];
        __half2 a = *(const __half2*)(p);
        __half2 b = *(const __half2*)(p + 2);
        return make_float4(__low2float(a), __high2float(a), __low2float(b), __high2float(b));
    };

    float4 rm3, rm2, rm1;
    if ((t0 & (LSEQ - 1)) == 0) {
        rm3 = make_float4(0.f, 0.f, 0.f, 0.f);
        rm2 = rm3; rm1 = rm3;
    } else {
        rm3 = ldrow(t0 - 3); rm2 = ldrow(t0 - 2); rm1 = ldrow(t0 - 1);
    }

#pragma unroll
    for (int i = 0; i < 8; i++) {
        int t = t0 + i;
        float4 cur = ldrow(t);
        float a0 = bb[0] + rm3.x * wk[0][0] + rm2.x * wk[0][1] + rm1.x * wk[0][2] + cur.x * wk[0][3];
        float a1 = bb[1] + rm3.y * wk[1][0] + rm2.y * wk[1][1] + rm1.y * wk[1][2] + cur.y * wk[1][3];
        float a2 = bb[2] + rm3.z * wk[2][0] + rm2.z * wk[2][1] + rm1.z * wk[2][2] + cur.z * wk[2][3];
        float a3 = bb[3] + rm3.w * wk[3][0] + rm2.w * wk[3][1] + rm1.w * wk[3][2] + cur.w * wk[3][3];
        a0 = a0 / (1.f + __expf(-a0));
        a1 = a1 / (1.f + __expf(-a1));
        a2 = a2 / (1.f + __expf(-a2));
        a3 = a3 / (1.f + __expf(-a3));
        __half* o = &gXCh[(size_t)t * CONVDIM + c4];
        *(__half2*)(o)     = __half2(__float2half_rn(a0), __float2half_rn(a1));
        *(__half2*)(o + 2) = __half2(__float2half_rn(a2), __float2half_rn(a3));
        rm3 = rm2; rm2 = rm1; rm1 = cur;
    }
}

// ================= SSD chunk kernel: all-MMA, fp16 states out ===================
#define CH_LDW 136
#define CH_LDN 72
#define CH_B16   0
#define CH_C16   (64*CH_LDW)
#define CH_XT    (2*64*CH_LDW)
#define CH_XDT   (CH_XT + 64*CH_LDN)
#define CH_BT    (CH_XDT + 64*CH_LDN)
#define CH_M16   (CH_BT + 128*CH_LDN)
#define CH_HALVES (CH_M16 + 64*CH_LDN)
#define CH_ACS_OFF (CH_HALVES*2)
#define CHUNK_SMEM (CH_ACS_OFF + 128*4)

__global__ __launch_bounds__(256)
void chunk_kernel()
{
    extern __shared__ char csm[];
    __half* H   = (__half*)csm;
    float* sAcs = (float*)(csm + CH_ACS_OFF);
    float* sDec = sAcs + 64;
    float* sOv  = (float*)csm;                 // fp32 overlay (Y staging)
    __half* sOvH = (__half*)csm;               // fp16 overlay (states staging)
    const uint32_t sb = smem_u32(csm);

    const int bc = blockIdx.x;
    const int h  = blockIdx.y;
    const int tid = threadIdx.x;
    const int wid = tid >> 5;
    const int lane = tid & 31;
    const int t0 = bc * CHUNKSZ;

    if (tid < 64) sAcs[tid] = gDalog[(size_t)(t0 + tid) * NH + h];
    __syncthreads();
    if (tid == 0) {
        float s = 0.f;
        for (int l = 0; l < 64; l++) { s += sAcs[l]; sAcs[l] = s; }
    }
    __syncthreads();
    if (tid < 64) sDec[tid] = __expf(sAcs[63] - sAcs[tid]);
    __syncthreads();

    for (int i = tid; i < 2048; i += 256) {
        int s  = i & 63;
        int c4 = (i >> 6) << 2;
        const __half* row = &gXCh[(size_t)(t0 + s) * CONVDIM + DINNER];
        __half2 b01 = *(const __half2*)(row + c4);
        __half2 b23 = *(const __half2*)(row + c4 + 2);
        *(__half2*)&H[CH_B16 + s * CH_LDW + c4]     = b01;
        *(__half2*)&H[CH_B16 + s * CH_LDW + c4 + 2] = b23;
        H[CH_BT + (c4 + 0) * CH_LDN + s] = __low2half(b01);
        H[CH_BT + (c4 + 1) * CH_LDN + s] = __high2half(b01);
        H[CH_BT + (c4 + 2) * CH_LDN + s] = __low2half(b23);
        H[CH_BT + (c4 + 3) * CH_LDN + s] = __high2half(b23);
        *(__half2*)&H[CH_C16 + s * CH_LDW + c4]     = *(const __half2*)(row + DSTATE + c4);
        *(__half2*)&H[CH_C16 + s * CH_LDW + c4 + 2] = *(const __half2*)(row + DSTATE + c4 + 2);
    }
    for (int i = tid; i < 1024; i += 256) {
        int s  = i & 63;
        int c4 = (i >> 6) << 2;
        float d = gDt[(size_t)(t0 + s) * NH + h];
        float dd = d * sDec[s];
        const __half* row = &gXCh[(size_t)(t0 + s) * CONVDIM + h * HD];
        __half2 x01 = *(const __half2*)(row + c4);
        __half2 x23 = *(const __half2*)(row + c4 + 2);
        float xs[4] = {__low2float(x01), __high2float(x01), __low2float(x23), __high2float(x23)};
#pragma unroll
        for (int j = 0; j < 4; j++) {
            H[CH_XT  + (c4 + j) * CH_LDN + s] = __float2half_rn(xs[j] * d);
            H[CH_XDT + (c4 + j) * CH_LDN + s] = __float2half_rn(xs[j] * dd);
        }
    }
    __syncthreads();

    const int a_r  = lane & 15;
    const int a_kq = (lane >> 4) * 8;
    const int b_n  = ((lane >> 4) << 3) + (lane & 7);
    const int b_kq = ((lane >> 3) & 1) * 8;
    const int er = lane >> 2;
    const int ec = (lane & 3) * 2;

    // MMA1: M[l][s] = sum_n C[l,n]*B[s,n]
    {
        const int warp_l = wid & 3;
        const int warp_s = wid >> 2;
        float acc[4][4];
#pragma unroll
        for (int ni = 0; ni < 4; ni++)
#pragma unroll
            for (int r = 0; r < 4; r++) acc[ni][r] = 0.f;
#pragma unroll
        for (int kk = 0; kk < 8; kk++) {
            const int k0 = kk * 16;
            uint32_t af[4], bf[2][4];
            ldmx4(af, sb + (CH_C16 + (warp_l * 16 + a_r) * CH_LDW) * 2 + (k0 + a_kq) * 2);
#pragma unroll
            for (int ni2 = 0; ni2 < 2; ni2++) {
                int s = warp_s * 32 + ni2 * 16 + b_n;
                ldmx4(bf[ni2], sb + (CH_B16 + s * CH_LDW) * 2 + (k0 + b_kq) * 2);
            }
#pragma unroll
            for (int ni = 0; ni < 4; ni++)
                mma16816(acc[ni], af, &bf[ni >> 1][(ni & 1) * 2]);
        }
#pragma unroll
        for (int ni = 0; ni < 4; ni++) {
#pragma unroll
            for (int r = 0; r < 4; r++) {
                int l = warp_l * 16 + (r >> 1) * 8 + er;
                int s = warp_s * 32 + ni * 8 + ec + (r & 1);
                float v = (s <= l) ? acc[ni][r] * __expf(sAcs[l] - sAcs[s]) : 0.f;
                H[CH_M16 + l * CH_LDN + s] = __float2half_rn(v);
            }
        }
    }
    __syncthreads();

    // MMA2: Y[l][p] = sum_s M[l,s]*Xt[p,s]
    float acc2[4][4];
    {
        const int warp_l = wid & 3;
        const int warp_p = wid >> 2;
#pragma unroll
        for (int ni = 0; ni < 4; ni++)
#pragma unroll
            for (int r = 0; r < 4; r++) acc2[ni][r] = 0.f;
#pragma unroll
        for (int kk = 0; kk < 4; kk++) {
            const int k0 = kk * 16;
            uint32_t af[4], bf[2][4];
            ldmx4(af, sb + (CH_M16 + (warp_l * 16 + a_r) * CH_LDN) * 2 + (k0 + a_kq) * 2);
#pragma unroll
            for (int ni2 = 0; ni2 < 2; ni2++) {
                int p = warp_p * 32 + ni2 * 16 + b_n;
                ldmx4(bf[ni2], sb + (CH_XT + p * CH_LDN) * 2 + (k0 + b_kq) * 2);
            }
#pragma unroll
            for (int ni = 0; ni < 4; ni++)
                mma16816(acc2[ni], af, &bf[ni >> 1][(ni & 1) * 2]);
        }
    }

    // MMA3: S[p][n] = sum_s Xdt[p,s]*Bt[n,s]
    float acc3[2][4][4];
    {
        const int warp_p = wid & 1;
        const int warp_n = wid >> 1;
#pragma unroll
        for (int mi = 0; mi < 2; mi++)
#pragma unroll
            for (int ni = 0; ni < 4; ni++)
#pragma unroll
                for (int r = 0; r < 4; r++) acc3[mi][ni][r] = 0.f;
#pragma unroll
        for (int kk = 0; kk < 4; kk++) {
            const int k0 = kk * 16;
            uint32_t af[2][4], bf[2][4];
#pragma unroll
            for (int mi = 0; mi < 2; mi++) {
                int p = warp_p * 32 + mi * 16 + a_r;
                ldmx4(af[mi], sb + (CH_XDT + p * CH_LDN) * 2 + (k0 + a_kq) * 2);
            }
#pragma unroll
            for (int ni2 = 0; ni2 < 2; ni2++) {
                int n = warp_n * 32 + ni2 * 16 + b_n;
                ldmx4(bf[ni2], sb + (CH_BT + n * CH_LDN) * 2 + (k0 + b_kq) * 2);
            }
#pragma unroll
            for (int mi = 0; mi < 2; mi++)
#pragma unroll
                for (int ni = 0; ni < 4; ni++)
                    mma16816(acc3[mi][ni], af[mi], &bf[ni >> 1][(ni & 1) * 2]);
        }
    }
    __syncthreads();

    // stage Y (fp32) -> coalesced write
    {
        const int warp_l = wid & 3;
        const int warp_p = wid >> 2;
#pragma unroll
        for (int ni = 0; ni < 4; ni++)
#pragma unroll
            for (int r = 0; r < 4; r++) {
                int l = warp_l * 16 + (r >> 1) * 8 + er;
                int p = warp_p * 32 + ni * 8 + ec + (r & 1);
                sOv[l * 68 + p] = acc2[ni][r];
            }
    }
    __syncthreads();
    {
        const int tx = tid & 15;
        const int ty = tid >> 4;
#pragma unroll
        for (int i = 0; i < 4; i++) {
            int l = ty * 4 + i;
            float4 v = *(const float4*)&sOv[l * 68 + tx * 4];
            *(float4*)&gYb[(size_t)(t0 + l) * DINNER + h * HD + tx * 4] = v;
        }
    }
    __syncthreads();

    // stage states (fp16, stride 136) -> coalesced write to gStH
    {
        const int warp_p = wid & 1;
        const int warp_n = wid >> 1;
#pragma unroll
        for (int mi = 0; mi < 2; mi++)
#pragma unroll
            for (int ni = 0; ni < 4; ni++)
#pragma unroll
                for (int r = 0; r < 4; r += 2) {
                    int p = warp_p * 32 + mi * 16 + (r >> 1) * 8 + er;
                    int n = warp_n * 32 + ni * 8 + ec;
                    *(__half2*)&sOvH[p * 136 + n] =
                        __half2(__float2half_rn(acc3[mi][ni][r]), __float2half_rn(acc3[mi][ni][r + 1]));
                }
    }
    __syncthreads();
    {
        size_t base = ((size_t)bc * NH + h) * (HD * DSTATE);
        for (int i = tid; i < 2048; i += 256) {
            int p  = i >> 5;
            int c4 = (i & 31) << 2;
            *(uint2*)&gStH[base + (size_t)p * DSTATE + c4] = *(const uint2*)&sOvH[p * 136 + c4];
        }
    }

    if (tid == 0) gAsum[bc * NH + h] = sAcs[63];
}

// ================= inter-chunk scan: fp16 in/out, fp32 accum ====================
__global__ __launch_bounds__(512)
void scan_kernel()
{
    const int bh = blockIdx.x;
    const int b = bh >> 6, h = bh & 63;
    const int tid = threadIdx.x;
    const int off = tid * 16;

    float prev[16];
#pragma unroll
    for (int q = 0; q < 16; q++) prev[q] = 0.f;

    for (int c = 0; c < NCHUNK; c++) {
        int bc = b * NCHUNK + c;
        size_t base = ((size_t)bc * NH + h) * (HD * DSTATE) + off;
        float dec = __expf(gAsum[bc * NH + h]);
        __half2 cur[8];
#pragma unroll
        for (int q = 0; q < 8; q++) cur[q] = *(__half2*)&gStH[base + q * 2];
#pragma unroll
        for (int q = 0; q < 8; q++)
            *(__half2*)&gStH[base + q * 2] =
                __half2(__float2half_rn(prev[q * 2]), __float2half_rn(prev[q * 2 + 1]));
#pragma unroll
        for (int q = 0; q < 8; q++) {
            prev[q * 2]     = prev[q * 2]     * dec + __low2float(cur[q]);
            prev[q * 2 + 1] = prev[q * 2 + 1] * dec + __high2float(cur[q]);
        }
    }
}

// ================= Y_off: fp16 MMA + smem-staged coalesced epilogue =============
#define YF_LDH 136
#define YF_TILE (64*YF_LDH*2)
#define YF_LDM 68
#define YOFF_SMEM (2*YF_TILE + 64*4 + 64)

__global__ __launch_bounds__(256)
void yoff_kernel(const float* __restrict__ Dparam)
{
    extern __shared__ char ysm[];
    __half* sC16  = (__half*)ysm;
    __half* sSt16 = (__half*)(ysm + YF_TILE);
    float*  sMf   = (float*)ysm;
    float*  sAcs  = (float*)(ysm + 2 * YF_TILE);
    const uint32_t sb = smem_u32(ysm);

    const int bc = blockIdx.x;
    const int h  = blockIdx.y;
    const int tid = threadIdx.x;
    const int wid = tid >> 5;
    const int lane = tid & 31;
    const int t0 = bc * CHUNKSZ;

    if (tid < 64) sAcs[tid] = gDalog[(size_t)(t0 + tid) * NH + h];
    __syncthreads();
    if (tid == 0) {
        float s = 0.f;
        for (int l = 0; l < 64; l++) { s += sAcs[l]; sAcs[l] = s; }
    }

    for (int i = tid; i < 2048; i += 256) {
        int r  = i >> 5;
        int c4 = (i & 31) << 2;
        const __half* crow = &gXCh[(size_t)(t0 + r) * CONVDIM + DINNER + DSTATE];
        *(__half2*)&sC16[r * YF_LDH + c4]     = *(const __half2*)(crow + c4);
        *(__half2*)&sC16[r * YF_LDH + c4 + 2] = *(const __half2*)(crow + c4 + 2);
        const __half* srow = &gStH[(((size_t)bc * NH + h) * HD + r) * DSTATE];
        *(__half2*)&sSt16[r * YF_LDH + c4]     = *(const __half2*)(srow + c4);
        *(__half2*)&sSt16[r * YF_LDH + c4 + 2] = *(const __half2*)(srow + c4 + 2);
    }
    __syncthreads();

    const int warp_l = wid & 3;
    const int warp_p = wid >> 2;
    const uint32_t cbase  = sb;
    const uint32_t stbase = sb + YF_TILE;

    const int a_r  = lane & 15;
    const int a_kq = (lane >> 4) * 8;
    const int b_n  = ((lane >> 4) << 3) + (lane & 7);
    const int b_kq = ((lane >> 3) & 1) * 8;

    float acc[4][4];
#pragma unroll
    for (int ni = 0; ni < 4; ni++)
#pragma unroll
        for (int r = 0; r < 4; r++) acc[ni][r] = 0.f;

#pragma unroll
    for (int kk = 0; kk < 8; kk++) {
        const int k0 = kk * 16;
        uint32_t af[4], bf[2][4];
        ldmx4(af, cbase + (warp_l * 16 + a_r) * (YF_LDH * 2) + (k0 + a_kq) * 2);
#pragma unroll
        for (int ni2 = 0; ni2 < 2; ni2++) {
            int p = warp_p * 32 + ni2 * 16 + b_n;
            ldmx4(bf[ni2], stbase + p * (YF_LDH * 2) + (k0 + b_kq) * 2);
        }
#pragma unroll
        for (int ni = 0; ni < 4; ni++)
            mma16816(acc[ni], af, &bf[ni >> 1][(ni & 1) * 2]);
    }
    __syncthreads();

    const int er = lane >> 2;
    const int ec = (lane & 3) * 2;
#pragma unroll
    for (int half_m = 0; half_m < 2; half_m++) {
        int l = warp_l * 16 + half_m * 8 + er;
#pragma unroll
        for (int ni = 0; ni < 4; ni++) {
            int p = warp_p * 32 + ni * 8 + ec;
            sMf[l * YF_LDM + p]     = acc[ni][half_m * 2 + 0];
            sMf[l * YF_LDM + p + 1] = acc[ni][half_m * 2 + 1];
        }
    }
    __syncthreads();

    const int tx = tid & 15;
    const int ty = tid >> 4;
    const float Dh = Dparam[h];
#pragma unroll
    for (int i = 0; i < 4; i++) {
        int l = ty * 4 + i;
        float sdo = __expf(sAcs[l]);
        size_t tz = (size_t)(t0 + l);
        float4 m4 = *(const float4*)&sMf[l * YF_LDM + tx * 4];
        const __half* xrow = &gXCh[tz * CONVDIM + h * HD + tx * 4];
        __half2 xa = *(const __half2*)(xrow);
        __half2 xb = *(const __half2*)(xrow + 2);
        float4 x4 = make_float4(__low2float(xa), __high2float(xa),
                                __low2float(xb), __high2float(xb));
        const __half* zrow = &gZXh[tz * ZXH_COLS + h * HD + tx * 4];
        __half2 za = *(const __half2*)(zrow);
        __half2 zb = *(const __half2*)(zrow + 2);
        float4 z4 = make_float4(__low2float(za), __high2float(za),
                                __low2float(zb), __high2float(zb));
        float4 y4 = *(const float4*)&gYb[tz * DINNER + h * HD + tx * 4];
        y4.x = (y4.x + sdo * m4.x + x4.x * Dh) * (z4.x / (1.f + __expf(-z4.x)));
        y4.y = (y4.y + sdo * m4.y + x4.y * Dh) * (z4.y / (1.f + __expf(-z4.y)));
        y4.z = (y4.z + sdo * m4.z + x4.z * Dh) * (z4.z / (1.f + __expf(-z4.z)));
        y4.w = (y4.w + sdo * m4.w + x4.w * Dh) * (z4.w / (1.f + __expf(-z4.w)));
        *(float4*)&gYb[tz * DINNER + h * HD + tx * 4] = y4;
    }
}

// ================= fused RMSNorm + fp16 convert =================================
__global__ __launch_bounds__(256)
void rms_convert_kernel(const float* __restrict__ norm_w, __half* __restrict__ dst)
{
    const int t = blockIdx.x;
    const int tid = threadIdx.x;
    const float* y = &gYb[(size_t)t * DINNER];

    float ss = 0.f;
    for (int i = tid * 4; i < DINNER; i += 256 * 4) {
        float4 v = *(const float4*)(y + i);
        ss += v.x * v.x + v.y * v.y + v.z * v.z + v.w * v.w;
    }
#pragma unroll
    for (int o = 16; o > 0; o >>= 1) ss += __shfl_down_sync(0xffffffffu, ss, o);

    __shared__ float red[8];
    if ((tid & 31) == 0) red[tid >> 5] = ss;
    __syncthreads();
    if (tid == 0) {
        float tot = 0.f;
#pragma unroll
        for (int w = 0; w < 8; w++) tot += red[w];
        red[0] = rsqrtf(tot / (float)DINNER + 1e-5f);
    }
    __syncthreads();
    const float scale = red[0];

    __half* d0 = dst + (size_t)t * DINNER;
    for (int i = tid * 4; i < DINNER; i += 256 * 4) {
        float4 v = *(const float4*)(y + i);
        float4 w = *(const float4*)(norm_w + i);
        __half2 hA = __half2(__float2half_rn(v.x * scale * w.x),
                             __float2half_rn(v.y * scale * w.y));
        __half2 hB = __half2(__float2half_rn(v.z * scale * w.z),
                             __float2half_rn(v.w * scale * w.w));
        *(__half2*)(d0 + i)     = hA;
        *(__half2*)(d0 + i + 2) = hB;
    }
}

// ================= launch =======================================================
extern "C" void kernel_launch(void* const* d_in, const int* in_sizes, int n_in,
                              void* d_out, int out_size)
{
    const float* u       = (const float*)d_in[0];
    const float* W_in    = (const float*)d_in[1];
    const float* conv_w  = (const float*)d_in[2];
    const float* conv_b  = (const float*)d_in[3];
    const float* dt_bias = (const float*)d_in[4];
    const float* A_log   = (const float*)d_in[5];
    const float* Dparam  = (const float*)d_in[6];
    const float* norm_w  = (const float*)d_in[7];
    const float* W_out   = (const float*)d_in[8];
    float* out = (float*)d_out;

    void *pA1, *pB1, *pA2, *pB2;
    cudaGetSymbolAddress(&pA1, gA1);
    cudaGetSymbolAddress(&pB1, gB1);
    cudaGetSymbolAddress(&pA2, gA2);
    cudaGetSymbolAddress(&pB2, gB2);

    cudaFuncSetAttribute(chunk_kernel, cudaFuncAttributeMaxDynamicSharedMemorySize, CHUNK_SMEM);
    cudaFuncSetAttribute(yoff_kernel,  cudaFuncAttributeMaxDynamicSharedMemorySize, YOFF_SMEM);
    cudaFuncSetAttribute(gemm_mma_kernel,   cudaFuncAttributeMaxDynamicSharedMemorySize, GM_SMEM);
    cudaFuncSetAttribute(gemm_mma_h_kernel, cudaFuncAttributeMaxDynamicSharedMemorySize, GM_SMEM);

    convert_kernel<<<(int)(((size_t)TT * K1 + 255) / 256), 256>>>(
        u, (__half*)pA1, (size_t)TT * K1, (size_t)TT * K1);
    convert_kernel<<<(int)(((size_t)DPROJ_PAD * K1 + 255) / 256), 256>>>(
        W_in, (__half*)pB1, (size_t)DPROJ * K1, (size_t)DPROJ_PAD * K1);
    convert_kernel<<<(int)(((size_t)DMODEL * K2 + 255) / 256), 256>>>(
        W_out, (__half*)pB2, (size_t)DMODEL * K2, (size_t)DMODEL * K2);

    // idx 3: in-projection
    {
        dim3 grid(DPROJ_PAD / 128, TT / 128);
        gemm_mma_h_kernel<<<grid, 256, GM_SMEM>>>((const __half*)pA1, (const __half*)pB1, K1);
    }
    dt_kernel<<<(TT * NH + 255) / 256, 256>>>(dt_bias, A_log);
    conv_kernel<<<((TT / 8) * (CONVDIM / 4) + 255) / 256, 256>>>(conv_w, conv_b);
    {
        dim3 grid(NBATCH * NCHUNK, NH);
        chunk_kernel<<<grid, 256, CHUNK_SMEM>>>();
    }
    scan_kernel<<<NBATCH * NH, 512>>>();
    {
        dim3 grid(NBATCH * NCHUNK, NH);
        yoff_kernel<<<grid, 256, YOFF_SMEM>>>(Dparam);
    }
    rms_convert_kernel<<<TT, 256>>>(norm_w, (__half*)pA2);
    {
        dim3 grid(DMODEL / 128, TT / 128);
        gemm_mma_kernel<<<grid, 256, GM_SMEM>>>((const __half*)pA2, (const __half*)pB2,
                                                out, DMODEL, K2);
    }
}